// round 10
// baseline (speedup 1.0000x reference)
#include <cuda_runtime.h>
#include <cstdint>

typedef unsigned int u32;

// Problem constants
static constexpr int Nn = 200000;
static constexpr int Ee = 400000;
static constexpr int Gg = 4096;
static constexpr int USR = 12;
static constexpr int NT = (Nn + 127) / 128;   // 1563 row tiles

// Scratch (device globals; no allocation allowed). Zero-initialized at load;
// each kernel that consumes a scratch buffer re-zeroes it for the next replay.
__device__ float g_agg[(size_t)Nn * 64];
__device__ float g_h[(size_t)Nn * 64];
__device__ float g_pool[(size_t)Gg * 129];
__device__ float g_wt[32768];   // tf32-converted transposed weights

// ---------------------------------------------------------------------------
__device__ __forceinline__ u32 tf32b(float x) {
    u32 u; asm("cvt.rna.tf32.f32 %0, %1;" : "=r"(u) : "f"(x)); return u;
}
__device__ __forceinline__ void mma_tf32(float& d0, float& d1, float& d2, float& d3,
                                         u32 a0, u32 a1, u32 a2, u32 a3, u32 b0, u32 b1) {
    asm volatile(
        "mma.sync.aligned.m16n8k8.row.col.f32.tf32.tf32.f32 "
        "{%0,%1,%2,%3},{%4,%5,%6,%7},{%8,%9},{%0,%1,%2,%3};"
        : "+f"(d0), "+f"(d1), "+f"(d2), "+f"(d3)
        : "r"(a0), "r"(a1), "r"(a2), "r"(a3), "r"(b0), "r"(b1));
}

// transpose + tf32-convert node weights into g_wt
__global__ void transpose_w(const float* __restrict__ n1w1, const float* __restrict__ n1w2,
                            const float* __restrict__ n2w1, const float* __restrict__ n2w2,
                            float* __restrict__ wt)
{
    int i = blockIdx.x * blockDim.x + threadIdx.x;
    float v;
    if (i < 4096)       { int n = i >> 6, k = i & 63; v = n1w1[k * 64 + n]; }
    else if (i < 8192)  { int j = i - 4096;  int n = j >> 6, k = j & 63;  v = n1w2[k * 64 + n]; }
    else if (i < 16384) { int j = i - 8192;  int n = j >> 6, k = j & 63;  v = n2w1[k * 128 + n]; }
    else                { int j = i - 16384; int n = j >> 7, k = j & 127; v = n2w2[k * 128 + n]; }
    wt[i] = __uint_as_float(tf32b(v));
}

// ---------------------------------------------------------------------------
// Edge message + scatter:  agg[dst] += relu(x[src] + ea @ EW + eb)
// Warp-autonomous, software-pipelined: next edge's indices/attrs/x-gather are
// issued before the current edge's FMA chain.
__global__ __launch_bounds__(256) void edge_kernel(
    const float* __restrict__ xin, const int* __restrict__ ei,
    const float* __restrict__ ea, const float* __restrict__ ew,
    const float* __restrict__ eb, float* __restrict__ agg)
{
    __shared__ float sW[16 * 64];
    int tid = threadIdx.x;
    for (int i = tid; i < 1024; i += 256) sW[i] = ew[i];
    __syncthreads();

    int lane = tid & 31, half = lane >> 4, q = lane & 15;
    int warpG = blockIdx.x * 8 + (tid >> 5);
    int nW = gridDim.x * 8;
    float4 bias = ((const float4*)eb)[q];
    const unsigned mask = 0xFFFFFFFFu;
    int srcBase = half << 4;

    int p = warpG;
    if (p * 2 >= Ee) return;
    int e = p * 2 + half;                 // Ee even -> both halves valid
    int s = __ldg(&ei[e]);
    int d = __ldg(&ei[Ee + e]);
    float av = __ldg(&ea[(size_t)e * 16 + q]);
    float4 xv = *(const float4*)(xin + (size_t)s * 64 + q * 4);

    while (true) {
        int pn = p + nW;
        bool more = (pn * 2 < Ee);
        int sn = 0, dn = 0; float avn = 0.f; float4 xvn;
        if (more) {
            int en = pn * 2 + half;
            sn = __ldg(&ei[en]);
            dn = __ldg(&ei[Ee + en]);
            avn = __ldg(&ea[(size_t)en * 16 + q]);
            xvn = *(const float4*)(xin + (size_t)sn * 64 + q * 4);
        }

        float4 acc = bias;
#pragma unroll
        for (int k = 0; k < 16; ++k) {
            float a = __shfl_sync(mask, av, srcBase + k);
            float4 w = ((const float4*)(sW + k * 64))[q];
            acc.x = fmaf(a, w.x, acc.x);
            acc.y = fmaf(a, w.y, acc.y);
            acc.z = fmaf(a, w.z, acc.z);
            acc.w = fmaf(a, w.w, acc.w);
        }
        acc.x = fmaxf(acc.x + xv.x, 0.f);
        acc.y = fmaxf(acc.y + xv.y, 0.f);
        acc.z = fmaxf(acc.z + xv.z, 0.f);
        acc.w = fmaxf(acc.w + xv.w, 0.f);

        float* pp = agg + (size_t)d * 64 + q * 4;
        asm volatile("red.global.add.v4.f32 [%0], {%1,%2,%3,%4};"
                     :: "l"(pp), "f"(acc.x), "f"(acc.y), "f"(acc.z), "f"(acc.w)
                     : "memory");

        if (!more) break;
        s = sn; d = dn; av = avn; xv = xvn; p = pn;
    }
}

// ---------------------------------------------------------------------------
// node1 (tf32 mma.sync, persistent, A2/OUT overlay A1 -> 70KB smem, 3 CTA/SM)
// h = relu( relu((x+agg)@W1+b1) @ W2 + b2 );   also re-zeroes agg rows.
// smem u32: A1 @0 [128*68] | B1 @8704 [64*68] | B2 @13056 [64*68] |
//           BI1 @17408 [64] | BI2 @17472 [64]     total 17536 u32
__global__ __launch_bounds__(256) void node1_mma(
    const float* __restrict__ xin, float* __restrict__ agg,
    const float* __restrict__ w1t, const float* __restrict__ b1,
    const float* __restrict__ w2t, const float* __restrict__ b2,
    float* __restrict__ hout)
{
    extern __shared__ u32 sm[];
    const int A1 = 0, B1 = 8704, B2 = 13056, BI1 = 17408, BI2 = 17472;

    int tid = threadIdx.x;
    // stage weights + biases ONCE
    for (int i = tid; i < 64 * 16; i += 256) {
        int r = i >> 4, c = (i & 15) * 4;
        float4 v = *(const float4*)(w1t + r * 64 + c);
        sm[B1 + r * 68 + c + 0] = __float_as_uint(v.x);
        sm[B1 + r * 68 + c + 1] = __float_as_uint(v.y);
        sm[B1 + r * 68 + c + 2] = __float_as_uint(v.z);
        sm[B1 + r * 68 + c + 3] = __float_as_uint(v.w);
        float4 w = *(const float4*)(w2t + r * 64 + c);
        sm[B2 + r * 68 + c + 0] = __float_as_uint(w.x);
        sm[B2 + r * 68 + c + 1] = __float_as_uint(w.y);
        sm[B2 + r * 68 + c + 2] = __float_as_uint(w.z);
        sm[B2 + r * 68 + c + 3] = __float_as_uint(w.w);
    }
    if (tid < 64) ((float*)(sm + BI1))[tid] = b1[tid];
    else if (tid < 128) ((float*)(sm + BI2))[tid - 64] = b2[tid - 64];

    int wid = tid >> 5, lane = tid & 31, g = lane >> 2, t = lane & 3;
    int wr = wid * 16;
    const float4 z4 = make_float4(0.f, 0.f, 0.f, 0.f);

    for (int tile = blockIdx.x; tile < NT; tile += gridDim.x) {
        int row0 = tile * 128;
        // stage A1 = tf32(x+agg); re-zero agg (valid rows only)
        for (int i = tid; i < 128 * 16; i += 256) {
            int r = i >> 4, c = (i & 15) * 4;
            int gr0 = row0 + r;
            int gr = gr0 < Nn ? gr0 : Nn - 1;
            float4 xv = *(const float4*)(xin + (size_t)gr * 64 + c);
            float4 av = *(const float4*)(agg + (size_t)gr * 64 + c);
            if (gr0 < Nn) *(float4*)(agg + (size_t)gr0 * 64 + c) = z4;
            sm[A1 + r * 68 + c + 0] = tf32b(xv.x + av.x);
            sm[A1 + r * 68 + c + 1] = tf32b(xv.y + av.y);
            sm[A1 + r * 68 + c + 2] = tf32b(xv.z + av.z);
            sm[A1 + r * 68 + c + 3] = tf32b(xv.w + av.w);
        }
        __syncthreads();

        float d[8][4];
#pragma unroll
        for (int n = 0; n < 8; ++n) { d[n][0] = d[n][1] = d[n][2] = d[n][3] = 0.f; }

        // GEMM1 (warp reads only its own 16 A rows)
#pragma unroll
        for (int ks = 0; ks < 8; ++ks) {
            int k0 = ks * 8;
            u32 a0 = sm[A1 + (wr + g) * 68 + k0 + t];
            u32 a1 = sm[A1 + (wr + g + 8) * 68 + k0 + t];
            u32 a2 = sm[A1 + (wr + g) * 68 + k0 + t + 4];
            u32 a3 = sm[A1 + (wr + g + 8) * 68 + k0 + t + 4];
#pragma unroll
            for (int nt = 0; nt < 8; ++nt) {
                u32 b0 = sm[B1 + (nt * 8 + g) * 68 + k0 + t];
                u32 bv = sm[B1 + (nt * 8 + g) * 68 + k0 + t + 4];
                mma_tf32(d[nt][0], d[nt][1], d[nt][2], d[nt][3], a0, a1, a2, a3, b0, bv);
            }
        }
        // epi1 -> back into A1 (own rows only; other warps never touch them)
        {
            const float* bb = (const float*)(sm + BI1);
#pragma unroll
            for (int nt = 0; nt < 8; ++nt) {
                int c = nt * 8 + t * 2;
                sm[A1 + (wr + g) * 68 + c]     = tf32b(fmaxf(d[nt][0] + bb[c], 0.f));
                sm[A1 + (wr + g) * 68 + c + 1] = tf32b(fmaxf(d[nt][1] + bb[c + 1], 0.f));
                sm[A1 + (wr + g + 8) * 68 + c]     = tf32b(fmaxf(d[nt][2] + bb[c], 0.f));
                sm[A1 + (wr + g + 8) * 68 + c + 1] = tf32b(fmaxf(d[nt][3] + bb[c + 1], 0.f));
                d[nt][0] = d[nt][1] = d[nt][2] = d[nt][3] = 0.f;
            }
        }
        // GEMM2 (A rows own-warp; B2 static)
#pragma unroll
        for (int ks = 0; ks < 8; ++ks) {
            int k0 = ks * 8;
            u32 a0 = sm[A1 + (wr + g) * 68 + k0 + t];
            u32 a1 = sm[A1 + (wr + g + 8) * 68 + k0 + t];
            u32 a2 = sm[A1 + (wr + g) * 68 + k0 + t + 4];
            u32 a3 = sm[A1 + (wr + g + 8) * 68 + k0 + t + 4];
#pragma unroll
            for (int nt = 0; nt < 8; ++nt) {
                u32 b0 = sm[B2 + (nt * 8 + g) * 68 + k0 + t];
                u32 bv = sm[B2 + (nt * 8 + g) * 68 + k0 + t + 4];
                mma_tf32(d[nt][0], d[nt][1], d[nt][2], d[nt][3], a0, a1, a2, a3, b0, bv);
            }
        }
        __syncthreads();   // all warps done with A1 before OUT (stride 64) overlays it
        // epi2: relu(+b2) -> OUT floats (overlay A1)
        {
            float* outF = (float*)(sm + A1);
            const float* bb = (const float*)(sm + BI2);
#pragma unroll
            for (int nt = 0; nt < 8; ++nt) {
                int c = nt * 8 + t * 2;
                outF[(wr + g) * 64 + c]     = fmaxf(d[nt][0] + bb[c], 0.f);
                outF[(wr + g) * 64 + c + 1] = fmaxf(d[nt][1] + bb[c + 1], 0.f);
                outF[(wr + g + 8) * 64 + c]     = fmaxf(d[nt][2] + bb[c], 0.f);
                outF[(wr + g + 8) * 64 + c + 1] = fmaxf(d[nt][3] + bb[c + 1], 0.f);
            }
        }
        __syncthreads();
        // coalesced store
        {
            const float* outF = (const float*)(sm + A1);
            for (int i = tid; i < 128 * 16; i += 256) {
                int r = i >> 4, c = (i & 15) * 4;
                int gr = row0 + r;
                if (gr < Nn) *(float4*)(hout + (size_t)gr * 64 + c) = *(const float4*)(outF + r * 64 + c);
            }
        }
        __syncthreads();   // store done before next iter's staging overwrites A1
    }
}

// ---------------------------------------------------------------------------
// node2 (tf32 mma.sync, persistent) + pooling; re-zeroes agg for next replay.
// smem u32: A1 @0 [128*68] | B1 @8704 [128*68] | A2 @17408 [128*132] |
//           B2 @34304 [128*132] | BI1 @51200 [128] | BI2 @51328 [128]
// OUT (float [128][128]=16384) overlays A2 (16896).
__global__ __launch_bounds__(256) void node2_mma(
    const float* __restrict__ hin, float* __restrict__ agg,
    const float* __restrict__ w1t, const float* __restrict__ b1,
    const float* __restrict__ w2t, const float* __restrict__ b2,
    const int* __restrict__ batch,
    float* __restrict__ pool, float* __restrict__ cnt)
{
    extern __shared__ u32 sm[];
    const int A1 = 0, B1 = 8704, A2 = 17408, B2 = 34304, BI1 = 51200, BI2 = 51328;

    int tid = threadIdx.x;
    for (int i = tid; i < 128 * 16; i += 256) {   // B1 = w1t [128][64]
        int r = i >> 4, c = (i & 15) * 4;
        float4 v = *(const float4*)(w1t + r * 64 + c);
        sm[B1 + r * 68 + c + 0] = __float_as_uint(v.x);
        sm[B1 + r * 68 + c + 1] = __float_as_uint(v.y);
        sm[B1 + r * 68 + c + 2] = __float_as_uint(v.z);
        sm[B1 + r * 68 + c + 3] = __float_as_uint(v.w);
    }
    for (int i = tid; i < 128 * 32; i += 256) {   // B2 = w2t [128][128]
        int r = i >> 5, c = (i & 31) * 4;
        float4 v = *(const float4*)(w2t + r * 128 + c);
        sm[B2 + r * 132 + c + 0] = __float_as_uint(v.x);
        sm[B2 + r * 132 + c + 1] = __float_as_uint(v.y);
        sm[B2 + r * 132 + c + 2] = __float_as_uint(v.z);
        sm[B2 + r * 132 + c + 3] = __float_as_uint(v.w);
    }
    if (tid < 128) ((float*)(sm + BI1))[tid] = b1[tid];
    else ((float*)(sm + BI2))[tid - 128] = b2[tid - 128];

    int wid = tid >> 5, lane = tid & 31, g = lane >> 2, t = lane & 3;
    int wr = wid * 16;
    const float4 z4 = make_float4(0.f, 0.f, 0.f, 0.f);

    for (int tile = blockIdx.x; tile < NT; tile += gridDim.x) {
        int row0 = tile * 128;
        for (int i = tid; i < 128 * 16; i += 256) {
            int r = i >> 4, c = (i & 15) * 4;
            int gr0 = row0 + r;
            int gr = gr0 < Nn ? gr0 : Nn - 1;
            float4 xv = *(const float4*)(hin + (size_t)gr * 64 + c);
            float4 av = *(const float4*)(agg + (size_t)gr * 64 + c);
            if (gr0 < Nn) *(float4*)(agg + (size_t)gr0 * 64 + c) = z4;
            sm[A1 + r * 68 + c + 0] = tf32b(xv.x + av.x);
            sm[A1 + r * 68 + c + 1] = tf32b(xv.y + av.y);
            sm[A1 + r * 68 + c + 2] = tf32b(xv.z + av.z);
            sm[A1 + r * 68 + c + 3] = tf32b(xv.w + av.w);
        }
        __syncthreads();

        float d[16][4];
#pragma unroll
        for (int n = 0; n < 16; ++n) { d[n][0] = d[n][1] = d[n][2] = d[n][3] = 0.f; }

        // GEMM1: [128x64] @ [64x128]
#pragma unroll
        for (int ks = 0; ks < 8; ++ks) {
            int k0 = ks * 8;
            u32 a0 = sm[A1 + (wr + g) * 68 + k0 + t];
            u32 a1 = sm[A1 + (wr + g + 8) * 68 + k0 + t];
            u32 a2 = sm[A1 + (wr + g) * 68 + k0 + t + 4];
            u32 a3 = sm[A1 + (wr + g + 8) * 68 + k0 + t + 4];
#pragma unroll
            for (int nt = 0; nt < 16; ++nt) {
                u32 b0 = sm[B1 + (nt * 8 + g) * 68 + k0 + t];
                u32 bv = sm[B1 + (nt * 8 + g) * 68 + k0 + t + 4];
                mma_tf32(d[nt][0], d[nt][1], d[nt][2], d[nt][3], a0, a1, a2, a3, b0, bv);
            }
        }
        // epi1 -> A2 (own rows)
        {
            const float* bb = (const float*)(sm + BI1);
#pragma unroll
            for (int nt = 0; nt < 16; ++nt) {
                int c = nt * 8 + t * 2;
                sm[A2 + (wr + g) * 132 + c]     = tf32b(fmaxf(d[nt][0] + bb[c], 0.f));
                sm[A2 + (wr + g) * 132 + c + 1] = tf32b(fmaxf(d[nt][1] + bb[c + 1], 0.f));
                sm[A2 + (wr + g + 8) * 132 + c]     = tf32b(fmaxf(d[nt][2] + bb[c], 0.f));
                sm[A2 + (wr + g + 8) * 132 + c + 1] = tf32b(fmaxf(d[nt][3] + bb[c + 1], 0.f));
                d[nt][0] = d[nt][1] = d[nt][2] = d[nt][3] = 0.f;
            }
        }
        // GEMM2: [128x128] @ [128x128]
#pragma unroll 4
        for (int ks = 0; ks < 16; ++ks) {
            int k0 = ks * 8;
            u32 a0 = sm[A2 + (wr + g) * 132 + k0 + t];
            u32 a1 = sm[A2 + (wr + g + 8) * 132 + k0 + t];
            u32 a2 = sm[A2 + (wr + g) * 132 + k0 + t + 4];
            u32 a3 = sm[A2 + (wr + g + 8) * 132 + k0 + t + 4];
#pragma unroll
            for (int nt = 0; nt < 16; ++nt) {
                u32 b0 = sm[B2 + (nt * 8 + g) * 132 + k0 + t];
                u32 bv = sm[B2 + (nt * 8 + g) * 132 + k0 + t + 4];
                mma_tf32(d[nt][0], d[nt][1], d[nt][2], d[nt][3], a0, a1, a2, a3, b0, bv);
            }
        }
        __syncthreads();
        // epi2: +b2 -> OUT floats (overlay A2)
        {
            float* outF = (float*)(sm + A2);
            const float* bb = (const float*)(sm + BI2);
#pragma unroll
            for (int nt = 0; nt < 16; ++nt) {
                int c = nt * 8 + t * 2;
                outF[(wr + g) * 128 + c]     = d[nt][0] + bb[c];
                outF[(wr + g) * 128 + c + 1] = d[nt][1] + bb[c + 1];
                outF[(wr + g + 8) * 128 + c]     = d[nt][2] + bb[c];
                outF[(wr + g + 8) * 128 + c + 1] = d[nt][3] + bb[c + 1];
            }
        }
        __syncthreads();
        // pooled scatter
        {
            const float* outF = (const float*)(sm + A2);
            int tx = tid & 31, ty = tid >> 5;
            int c0 = tx * 4;
#pragma unroll
            for (int i = 0; i < 16; ++i) {
                int r = ty * 16 + i;
                int gr = row0 + r;
                if (gr < Nn) {
                    int gg = batch[gr];
                    float4 v = *(const float4*)(outF + r * 128 + c0);
                    float* p = pool + (size_t)gg * 128 + c0;
                    asm volatile("red.global.add.v4.f32 [%0], {%1,%2,%3,%4};"
                                 :: "l"(p), "f"(v.x), "f"(v.y), "f"(v.z), "f"(v.w) : "memory");
                }
            }
            if (tid < 128) {
                int gr = row0 + tid;
                if (gr < Nn) atomicAdd(&cnt[batch[gr]], 1.0f);
            }
        }
        __syncthreads();
    }
}

// ---------------------------------------------------------------------------
// Head MLP: z = [pool/cnt, usr]; re-zeroes pool/cnt for next replay.
__global__ __launch_bounds__(128) void head_kernel(
    float* __restrict__ pool, float* __restrict__ cnt,
    const float* __restrict__ usr,
    const float* __restrict__ w1, const float* __restrict__ b1,
    const float* __restrict__ w2, const float* __restrict__ b2,
    const float* __restrict__ w3, const float* __restrict__ b3,
    const float* __restrict__ w4, const float* __restrict__ b4,
    const float* __restrict__ w5, const float* __restrict__ b5,
    float* __restrict__ out)
{
    __shared__ float z[140];
    __shared__ float a1[128];
    __shared__ float a2[64];
    __shared__ float a3[32];
    __shared__ float a4s[16];

    int g = blockIdx.x, t = threadIdx.x;
    float inv = 1.0f / fmaxf(cnt[g], 1.0f);
    z[t] = pool[(size_t)g * 128 + t] * inv;
    if (t < USR) z[128 + t] = usr[(size_t)g * USR + t];
    __syncthreads();
    // re-zero pool/cnt (all reads complete after the barrier)
    pool[(size_t)g * 128 + t] = 0.f;
    if (t == 0) cnt[g] = 0.f;

    {
        float s = b1[t];
        for (int k = 0; k < 140; ++k) s = fmaf(z[k], w1[k * 128 + t], s);
        a1[t] = fmaxf(s, 0.f);
    }
    __syncthreads();
    if (t < 64) {
        float s = b2[t];
        for (int k = 0; k < 128; ++k) s = fmaf(a1[k], w2[k * 64 + t], s);
        a2[t] = fmaxf(s, 0.f);
    }
    __syncthreads();
    if (t < 32) {
        float s = b3[t];
        for (int k = 0; k < 64; ++k) s = fmaf(a2[k], w3[k * 32 + t], s);
        a3[t] = fmaxf(s, 0.f);
    }
    __syncthreads();
    if (t < 16) {
        float s = b4[t];
        for (int k = 0; k < 32; ++k) s = fmaf(a3[k], w4[k * 16 + t], s);
        a4s[t] = fmaxf(s, 0.f);
    }
    __syncthreads();
    if (t == 0) {
        float s = b5[0];
        for (int k = 0; k < 16; ++k) s = fmaf(a4s[k], w5[k], s);
        out[g] = s;
    }
}

// ---------------------------------------------------------------------------
extern "C" void kernel_launch(void* const* d_in, const int* in_sizes, int n_in,
                              void* d_out, int out_size)
{
    const float* x     = (const float*)d_in[0];
    const int*   ei    = (const int*)d_in[1];
    const float* ea    = (const float*)d_in[2];
    const int*   batch = (const int*)d_in[3];
    const float* usr   = (const float*)d_in[4];
    const float* e1_w = (const float*)d_in[5],  *e1_b = (const float*)d_in[6];
    const float* n1_w1 = (const float*)d_in[7], *n1_b1 = (const float*)d_in[8];
    const float* n1_w2 = (const float*)d_in[9], *n1_b2 = (const float*)d_in[10];
    const float* e2_w = (const float*)d_in[11], *e2_b = (const float*)d_in[12];
    const float* n2_w1 = (const float*)d_in[13], *n2_b1 = (const float*)d_in[14];
    const float* n2_w2 = (const float*)d_in[15], *n2_b2 = (const float*)d_in[16];
    const float* h1_w = (const float*)d_in[17], *h1_b = (const float*)d_in[18];
    const float* h2_w = (const float*)d_in[19], *h2_b = (const float*)d_in[20];
    const float* h3_w = (const float*)d_in[21], *h3_b = (const float*)d_in[22];
    const float* h4_w = (const float*)d_in[23], *h4_b = (const float*)d_in[24];
    const float* h5_w = (const float*)d_in[25], *h5_b = (const float*)d_in[26];
    float* out = (float*)d_out;

    float *agg, *h, *poolbuf, *wt;
    cudaGetSymbolAddress((void**)&agg, g_agg);
    cudaGetSymbolAddress((void**)&h, g_h);
    cudaGetSymbolAddress((void**)&poolbuf, g_pool);
    cudaGetSymbolAddress((void**)&wt, g_wt);
    float* pool = poolbuf;
    float* cnt  = poolbuf + (size_t)Gg * 128;
    float* n1w1t = wt;
    float* n1w2t = wt + 4096;
    float* n2w1t = wt + 8192;
    float* n2w2t = wt + 16384;

    const int NODE1_SMEM = 17536 * 4;   // 70144 B -> 3 CTA/SM
    const int NODE2_SMEM = 51456 * 4;   // 205824 B -> 1 CTA/SM
    cudaFuncSetAttribute(node1_mma, cudaFuncAttributeMaxDynamicSharedMemorySize, NODE1_SMEM);
    cudaFuncSetAttribute(node2_mma, cudaFuncAttributeMaxDynamicSharedMemorySize, NODE2_SMEM);

    const int EDGE_GRID = 1184;

    transpose_w<<<128, 256>>>(n1_w1, n1_w2, n2_w1, n2_w2, wt);

    // layer 1 (agg is zero: globals zero-init on first call, re-zeroed by node2 each replay)
    edge_kernel<<<EDGE_GRID, 256>>>(x, ei, ea, e1_w, e1_b, agg);
    node1_mma<<<444, 256, NODE1_SMEM>>>(x, agg, n1w1t, n1_b1, n1w2t, n1_b2, h);
    // node1 re-zeroed agg for layer 2

    // layer 2
    edge_kernel<<<EDGE_GRID, 256>>>(h, ei, ea, e2_w, e2_b, agg);
    node2_mma<<<148, 256, NODE2_SMEM>>>(h, agg, n2w1t, n2_b1, n2w2t, n2_b2, batch, pool, cnt);
    // node2 re-zeroed agg; pool/cnt zeroed by head below

    // head
    head_kernel<<<Gg, 128>>>(pool, cnt, usr,
                             h1_w, h1_b, h2_w, h2_b, h3_w, h3_b, h4_w, h4_b, h5_w, h5_b,
                             out);
}

// round 13
// speedup vs baseline: 1.4294x; 1.4294x over previous
#include <cuda_runtime.h>
#include <cstdint>

typedef unsigned int u32;

// Problem constants
static constexpr int Nn = 200000;
static constexpr int Ee = 400000;
static constexpr int Gg = 4096;
static constexpr int USR = 12;
static constexpr int NT = (Nn + 127) / 128;   // 1563 row tiles

// Scratch (device globals; no allocation allowed)
__device__ float g_agg[(size_t)Nn * 64];
__device__ float g_h[(size_t)Nn * 64];
__device__ float g_pool[(size_t)Gg * 129];
__device__ float g_wt[32768];   // tf32-converted transposed weights

// ---------------------------------------------------------------------------
__device__ __forceinline__ u32 tf32b(float x) {
    u32 u; asm("cvt.rna.tf32.f32 %0, %1;" : "=r"(u) : "f"(x)); return u;
}
__device__ __forceinline__ void mma_tf32(float& d0, float& d1, float& d2, float& d3,
                                         u32 a0, u32 a1, u32 a2, u32 a3, u32 b0, u32 b1) {
    asm volatile(
        "mma.sync.aligned.m16n8k8.row.col.f32.tf32.tf32.f32 "
        "{%0,%1,%2,%3},{%4,%5,%6,%7},{%8,%9},{%0,%1,%2,%3};"
        : "+f"(d0), "+f"(d1), "+f"(d2), "+f"(d3)
        : "r"(a0), "r"(a1), "r"(a2), "r"(a3), "r"(b0), "r"(b1));
}

// ---------------------------------------------------------------------------
__global__ void zero_kernel(float4* __restrict__ p, int n4) {
    int i = blockIdx.x * blockDim.x + threadIdx.x;
    if (i < n4) p[i] = make_float4(0.f, 0.f, 0.f, 0.f);
}

// transpose + tf32-convert node weights into g_wt
__global__ void transpose_w(const float* __restrict__ n1w1, const float* __restrict__ n1w2,
                            const float* __restrict__ n2w1, const float* __restrict__ n2w2,
                            float* __restrict__ wt)
{
    int i = blockIdx.x * blockDim.x + threadIdx.x;
    float v;
    if (i < 4096)       { int n = i >> 6, k = i & 63; v = n1w1[k * 64 + n]; }
    else if (i < 8192)  { int j = i - 4096;  int n = j >> 6, k = j & 63;  v = n1w2[k * 64 + n]; }
    else if (i < 16384) { int j = i - 8192;  int n = j >> 6, k = j & 63;  v = n2w1[k * 128 + n]; }
    else                { int j = i - 16384; int n = j >> 7, k = j & 127; v = n2w2[k * 128 + n]; }
    wt[i] = __uint_as_float(tf32b(v));
}

// ---------------------------------------------------------------------------
// Edge message + scatter:  agg[dst] += relu(x[src] + ea @ EW + eb)
// Warp-autonomous, software-pipelined (round-10 version, measured 72us).
__global__ __launch_bounds__(256) void edge_kernel(
    const float* __restrict__ xin, const int* __restrict__ ei,
    const float* __restrict__ ea, const float* __restrict__ ew,
    const float* __restrict__ eb, float* __restrict__ agg)
{
    __shared__ float sW[16 * 64];
    int tid = threadIdx.x;
    for (int i = tid; i < 1024; i += 256) sW[i] = ew[i];
    __syncthreads();

    int lane = tid & 31, half = lane >> 4, q = lane & 15;
    int warpG = blockIdx.x * 8 + (tid >> 5);
    int nW = gridDim.x * 8;
    float4 bias = ((const float4*)eb)[q];
    const unsigned mask = 0xFFFFFFFFu;
    int srcBase = half << 4;

    int p = warpG;
    if (p * 2 >= Ee) return;
    int e = p * 2 + half;                 // Ee even -> both halves valid
    int s = __ldg(&ei[e]);
    int d = __ldg(&ei[Ee + e]);
    float av = __ldg(&ea[(size_t)e * 16 + q]);
    float4 xv = *(const float4*)(xin + (size_t)s * 64 + q * 4);

    while (true) {
        int pn = p + nW;
        bool more = (pn * 2 < Ee);
        int sn = 0, dn = 0; float avn = 0.f; float4 xvn;
        if (more) {
            int en = pn * 2 + half;
            sn = __ldg(&ei[en]);
            dn = __ldg(&ei[Ee + en]);
            avn = __ldg(&ea[(size_t)en * 16 + q]);
            xvn = *(const float4*)(xin + (size_t)sn * 64 + q * 4);
        }

        float4 acc = bias;
#pragma unroll
        for (int k = 0; k < 16; ++k) {
            float a = __shfl_sync(mask, av, srcBase + k);
            float4 w = ((const float4*)(sW + k * 64))[q];
            acc.x = fmaf(a, w.x, acc.x);
            acc.y = fmaf(a, w.y, acc.y);
            acc.z = fmaf(a, w.z, acc.z);
            acc.w = fmaf(a, w.w, acc.w);
        }
        acc.x = fmaxf(acc.x + xv.x, 0.f);
        acc.y = fmaxf(acc.y + xv.y, 0.f);
        acc.z = fmaxf(acc.z + xv.z, 0.f);
        acc.w = fmaxf(acc.w + xv.w, 0.f);

        float* pp = agg + (size_t)d * 64 + q * 4;
        asm volatile("red.global.add.v4.f32 [%0], {%1,%2,%3,%4};"
                     :: "l"(pp), "f"(acc.x), "f"(acc.y), "f"(acc.z), "f"(acc.w)
                     : "memory");

        if (!more) break;
        s = sn; d = dn; av = avn; xv = xvn; p = pn;
    }
}

// ---------------------------------------------------------------------------
// node1 (tf32 mma.sync, persistent) — round-9 version (52us measured).
// smem u32: A1 @0 [128*68] | B1 @8704 [64*68] | A2 @13056 [128*68] |
//           B2 @21760 [64*68] | BI1 @26112 [64] | BI2 @26176 [64]
// OUT (float [128][64]) overlays A2 after GEMM2.
__global__ __launch_bounds__(256) void node1_mma(
    const float* __restrict__ xin, const float* __restrict__ agg,
    const float* __restrict__ w1t, const float* __restrict__ b1,
    const float* __restrict__ w2t, const float* __restrict__ b2,
    float* __restrict__ hout)
{
    extern __shared__ u32 sm[];
    const int A1 = 0, B1 = 8704, A2 = 13056, B2 = 21760, BI1 = 26112, BI2 = 26176;

    int tid = threadIdx.x;
    // stage weights + biases ONCE
    for (int i = tid; i < 64 * 16; i += 256) {
        int r = i >> 4, c = (i & 15) * 4;
        float4 v = *(const float4*)(w1t + r * 64 + c);
        sm[B1 + r * 68 + c + 0] = __float_as_uint(v.x);
        sm[B1 + r * 68 + c + 1] = __float_as_uint(v.y);
        sm[B1 + r * 68 + c + 2] = __float_as_uint(v.z);
        sm[B1 + r * 68 + c + 3] = __float_as_uint(v.w);
        float4 w = *(const float4*)(w2t + r * 64 + c);
        sm[B2 + r * 68 + c + 0] = __float_as_uint(w.x);
        sm[B2 + r * 68 + c + 1] = __float_as_uint(w.y);
        sm[B2 + r * 68 + c + 2] = __float_as_uint(w.z);
        sm[B2 + r * 68 + c + 3] = __float_as_uint(w.w);
    }
    if (tid < 64) ((float*)(sm + BI1))[tid] = b1[tid];
    else if (tid < 128) ((float*)(sm + BI2))[tid - 64] = b2[tid - 64];

    int wid = tid >> 5, lane = tid & 31, g = lane >> 2, t = lane & 3;
    int wr = wid * 16;

    for (int tile = blockIdx.x; tile < NT; tile += gridDim.x) {
        int row0 = tile * 128;
        // stage A1 = tf32(x+agg)
        for (int i = tid; i < 128 * 16; i += 256) {
            int r = i >> 4, c = (i & 15) * 4;
            int gr = row0 + r; if (gr >= Nn) gr = Nn - 1;
            float4 xv = *(const float4*)(xin + (size_t)gr * 64 + c);
            float4 av = *(const float4*)(agg + (size_t)gr * 64 + c);
            sm[A1 + r * 68 + c + 0] = tf32b(xv.x + av.x);
            sm[A1 + r * 68 + c + 1] = tf32b(xv.y + av.y);
            sm[A1 + r * 68 + c + 2] = tf32b(xv.z + av.z);
            sm[A1 + r * 68 + c + 3] = tf32b(xv.w + av.w);
        }
        __syncthreads();

        float d[8][4];
#pragma unroll
        for (int n = 0; n < 8; ++n) { d[n][0] = d[n][1] = d[n][2] = d[n][3] = 0.f; }

        // GEMM1
#pragma unroll
        for (int ks = 0; ks < 8; ++ks) {
            int k0 = ks * 8;
            u32 a0 = sm[A1 + (wr + g) * 68 + k0 + t];
            u32 a1 = sm[A1 + (wr + g + 8) * 68 + k0 + t];
            u32 a2 = sm[A1 + (wr + g) * 68 + k0 + t + 4];
            u32 a3 = sm[A1 + (wr + g + 8) * 68 + k0 + t + 4];
#pragma unroll
            for (int nt = 0; nt < 8; ++nt) {
                u32 b0 = sm[B1 + (nt * 8 + g) * 68 + k0 + t];
                u32 bv = sm[B1 + (nt * 8 + g) * 68 + k0 + t + 4];
                mma_tf32(d[nt][0], d[nt][1], d[nt][2], d[nt][3], a0, a1, a2, a3, b0, bv);
            }
        }
        // epi1 -> A2 (own rows only)
        {
            const float* bb = (const float*)(sm + BI1);
#pragma unroll
            for (int nt = 0; nt < 8; ++nt) {
                int c = nt * 8 + t * 2;
                sm[A2 + (wr + g) * 68 + c]     = tf32b(fmaxf(d[nt][0] + bb[c], 0.f));
                sm[A2 + (wr + g) * 68 + c + 1] = tf32b(fmaxf(d[nt][1] + bb[c + 1], 0.f));
                sm[A2 + (wr + g + 8) * 68 + c]     = tf32b(fmaxf(d[nt][2] + bb[c], 0.f));
                sm[A2 + (wr + g + 8) * 68 + c + 1] = tf32b(fmaxf(d[nt][3] + bb[c + 1], 0.f));
                d[nt][0] = d[nt][1] = d[nt][2] = d[nt][3] = 0.f;
            }
        }
        // GEMM2 (A rows own-warp; B2 static) — no sync needed
#pragma unroll
        for (int ks = 0; ks < 8; ++ks) {
            int k0 = ks * 8;
            u32 a0 = sm[A2 + (wr + g) * 68 + k0 + t];
            u32 a1 = sm[A2 + (wr + g + 8) * 68 + k0 + t];
            u32 a2 = sm[A2 + (wr + g) * 68 + k0 + t + 4];
            u32 a3 = sm[A2 + (wr + g + 8) * 68 + k0 + t + 4];
#pragma unroll
            for (int nt = 0; nt < 8; ++nt) {
                u32 b0 = sm[B2 + (nt * 8 + g) * 68 + k0 + t];
                u32 bv = sm[B2 + (nt * 8 + g) * 68 + k0 + t + 4];
                mma_tf32(d[nt][0], d[nt][1], d[nt][2], d[nt][3], a0, a1, a2, a3, b0, bv);
            }
        }
        __syncthreads();   // all warps done reading A2 before OUT overlays it
        // epi2: relu(+b2) -> OUT floats (overlay A2)
        {
            float* outF = (float*)(sm + A2);
            const float* bb = (const float*)(sm + BI2);
#pragma unroll
            for (int nt = 0; nt < 8; ++nt) {
                int c = nt * 8 + t * 2;
                outF[(wr + g) * 64 + c]     = fmaxf(d[nt][0] + bb[c], 0.f);
                outF[(wr + g) * 64 + c + 1] = fmaxf(d[nt][1] + bb[c + 1], 0.f);
                outF[(wr + g + 8) * 64 + c]     = fmaxf(d[nt][2] + bb[c], 0.f);
                outF[(wr + g + 8) * 64 + c + 1] = fmaxf(d[nt][3] + bb[c + 1], 0.f);
            }
        }
        __syncthreads();
        // coalesced store
        {
            const float* outF = (const float*)(sm + A2);
            for (int i = tid; i < 128 * 16; i += 256) {
                int r = i >> 4, c = (i & 15) * 4;
                int gr = row0 + r;
                if (gr < Nn) *(float4*)(hout + (size_t)gr * 64 + c) = *(const float4*)(outF + r * 64 + c);
            }
        }
        __syncthreads();   // store done before next iter's epi1 overwrites A2
    }
}

// ---------------------------------------------------------------------------
// node2 (tf32 mma.sync, persistent) + pooling — round-9 version.
// smem u32: A1 @0 [128*68] | B1 @8704 [128*68] | A2 @17408 [128*132] |
//           B2 @34304 [128*132] | BI1 @51200 [128] | BI2 @51328 [128]
// OUT (float [128][128]=16384) overlays A2 (16896).
__global__ __launch_bounds__(256) void node2_mma(
    const float* __restrict__ hin, const float* __restrict__ agg,
    const float* __restrict__ w1t, const float* __restrict__ b1,
    const float* __restrict__ w2t, const float* __restrict__ b2,
    const int* __restrict__ batch,
    float* __restrict__ pool, float* __restrict__ cnt)
{
    extern __shared__ u32 sm[];
    const int A1 = 0, B1 = 8704, A2 = 17408, B2 = 34304, BI1 = 51200, BI2 = 51328;

    int tid = threadIdx.x;
    for (int i = tid; i < 128 * 16; i += 256) {   // B1 = w1t [128][64]
        int r = i >> 4, c = (i & 15) * 4;
        float4 v = *(const float4*)(w1t + r * 64 + c);
        sm[B1 + r * 68 + c + 0] = __float_as_uint(v.x);
        sm[B1 + r * 68 + c + 1] = __float_as_uint(v.y);
        sm[B1 + r * 68 + c + 2] = __float_as_uint(v.z);
        sm[B1 + r * 68 + c + 3] = __float_as_uint(v.w);
    }
    for (int i = tid; i < 128 * 32; i += 256) {   // B2 = w2t [128][128]
        int r = i >> 5, c = (i & 31) * 4;
        float4 v = *(const float4*)(w2t + r * 128 + c);
        sm[B2 + r * 132 + c + 0] = __float_as_uint(v.x);
        sm[B2 + r * 132 + c + 1] = __float_as_uint(v.y);
        sm[B2 + r * 132 + c + 2] = __float_as_uint(v.z);
        sm[B2 + r * 132 + c + 3] = __float_as_uint(v.w);
    }
    if (tid < 128) ((float*)(sm + BI1))[tid] = b1[tid];
    else ((float*)(sm + BI2))[tid - 128] = b2[tid - 128];

    int wid = tid >> 5, lane = tid & 31, g = lane >> 2, t = lane & 3;
    int wr = wid * 16;

    for (int tile = blockIdx.x; tile < NT; tile += gridDim.x) {
        int row0 = tile * 128;
        for (int i = tid; i < 128 * 16; i += 256) {
            int r = i >> 4, c = (i & 15) * 4;
            int gr = row0 + r; if (gr >= Nn) gr = Nn - 1;
            float4 xv = *(const float4*)(hin + (size_t)gr * 64 + c);
            float4 av = *(const float4*)(agg + (size_t)gr * 64 + c);
            sm[A1 + r * 68 + c + 0] = tf32b(xv.x + av.x);
            sm[A1 + r * 68 + c + 1] = tf32b(xv.y + av.y);
            sm[A1 + r * 68 + c + 2] = tf32b(xv.z + av.z);
            sm[A1 + r * 68 + c + 3] = tf32b(xv.w + av.w);
        }
        __syncthreads();

        float d[16][4];
#pragma unroll
        for (int n = 0; n < 16; ++n) { d[n][0] = d[n][1] = d[n][2] = d[n][3] = 0.f; }

        // GEMM1: [128x64] @ [64x128]
#pragma unroll
        for (int ks = 0; ks < 8; ++ks) {
            int k0 = ks * 8;
            u32 a0 = sm[A1 + (wr + g) * 68 + k0 + t];
            u32 a1 = sm[A1 + (wr + g + 8) * 68 + k0 + t];
            u32 a2 = sm[A1 + (wr + g) * 68 + k0 + t + 4];
            u32 a3 = sm[A1 + (wr + g + 8) * 68 + k0 + t + 4];
#pragma unroll
            for (int nt = 0; nt < 16; ++nt) {
                u32 b0 = sm[B1 + (nt * 8 + g) * 68 + k0 + t];
                u32 bv = sm[B1 + (nt * 8 + g) * 68 + k0 + t + 4];
                mma_tf32(d[nt][0], d[nt][1], d[nt][2], d[nt][3], a0, a1, a2, a3, b0, bv);
            }
        }
        // epi1 -> A2 (own rows)
        {
            const float* bb = (const float*)(sm + BI1);
#pragma unroll
            for (int nt = 0; nt < 16; ++nt) {
                int c = nt * 8 + t * 2;
                sm[A2 + (wr + g) * 132 + c]     = tf32b(fmaxf(d[nt][0] + bb[c], 0.f));
                sm[A2 + (wr + g) * 132 + c + 1] = tf32b(fmaxf(d[nt][1] + bb[c + 1], 0.f));
                sm[A2 + (wr + g + 8) * 132 + c]     = tf32b(fmaxf(d[nt][2] + bb[c], 0.f));
                sm[A2 + (wr + g + 8) * 132 + c + 1] = tf32b(fmaxf(d[nt][3] + bb[c + 1], 0.f));
                d[nt][0] = d[nt][1] = d[nt][2] = d[nt][3] = 0.f;
            }
        }
        // GEMM2: [128x128] @ [128x128]  (A rows own-warp; B2 static)
#pragma unroll 4
        for (int ks = 0; ks < 16; ++ks) {
            int k0 = ks * 8;
            u32 a0 = sm[A2 + (wr + g) * 132 + k0 + t];
            u32 a1 = sm[A2 + (wr + g + 8) * 132 + k0 + t];
            u32 a2 = sm[A2 + (wr + g) * 132 + k0 + t + 4];
            u32 a3 = sm[A2 + (wr + g + 8) * 132 + k0 + t + 4];
#pragma unroll
            for (int nt = 0; nt < 16; ++nt) {
                u32 b0 = sm[B2 + (nt * 8 + g) * 132 + k0 + t];
                u32 bv = sm[B2 + (nt * 8 + g) * 132 + k0 + t + 4];
                mma_tf32(d[nt][0], d[nt][1], d[nt][2], d[nt][3], a0, a1, a2, a3, b0, bv);
            }
        }
        __syncthreads();   // all warps done reading A2 before OUT overlays it
        // epi2: +b2 -> OUT floats (overlay A2)
        {
            float* outF = (float*)(sm + A2);
            const float* bb = (const float*)(sm + BI2);
#pragma unroll
            for (int nt = 0; nt < 16; ++nt) {
                int c = nt * 8 + t * 2;
                outF[(wr + g) * 128 + c]     = d[nt][0] + bb[c];
                outF[(wr + g) * 128 + c + 1] = d[nt][1] + bb[c + 1];
                outF[(wr + g + 8) * 128 + c]     = d[nt][2] + bb[c];
                outF[(wr + g + 8) * 128 + c + 1] = d[nt][3] + bb[c + 1];
            }
        }
        __syncthreads();
        // pooled scatter
        {
            const float* outF = (const float*)(sm + A2);
            int tx = tid & 31, ty = tid >> 5;
            int c0 = tx * 4;
#pragma unroll
            for (int i = 0; i < 16; ++i) {
                int r = ty * 16 + i;
                int gr = row0 + r;
                if (gr < Nn) {
                    int gg = batch[gr];
                    float4 v = *(const float4*)(outF + r * 128 + c0);
                    float* p = pool + (size_t)gg * 128 + c0;
                    asm volatile("red.global.add.v4.f32 [%0], {%1,%2,%3,%4};"
                                 :: "l"(p), "f"(v.x), "f"(v.y), "f"(v.z), "f"(v.w) : "memory");
                }
            }
            if (tid < 128) {
                int gr = row0 + tid;
                if (gr < Nn) atomicAdd(&cnt[batch[gr]], 1.0f);
            }
        }
        __syncthreads();   // scatter done before next iter's epi1 overwrites A2
    }
}

// ---------------------------------------------------------------------------
// Head MLP: z = [pool/cnt, usr]; 140 ->128 ->64 ->32 ->16 ->1
__global__ __launch_bounds__(128) void head_kernel(
    const float* __restrict__ pool, const float* __restrict__ cnt,
    const float* __restrict__ usr,
    const float* __restrict__ w1, const float* __restrict__ b1,
    const float* __restrict__ w2, const float* __restrict__ b2,
    const float* __restrict__ w3, const float* __restrict__ b3,
    const float* __restrict__ w4, const float* __restrict__ b4,
    const float* __restrict__ w5, const float* __restrict__ b5,
    float* __restrict__ out)
{
    __shared__ float z[140];
    __shared__ float a1[128];
    __shared__ float a2[64];
    __shared__ float a3[32];
    __shared__ float a4s[16];

    int g = blockIdx.x, t = threadIdx.x;
    float inv = 1.0f / fmaxf(cnt[g], 1.0f);
    z[t] = pool[(size_t)g * 128 + t] * inv;
    if (t < USR) z[128 + t] = usr[(size_t)g * USR + t];
    __syncthreads();

    {
        float s = b1[t];
        for (int k = 0; k < 140; ++k) s = fmaf(z[k], w1[k * 128 + t], s);
        a1[t] = fmaxf(s, 0.f);
    }
    __syncthreads();
    if (t < 64) {
        float s = b2[t];
        for (int k = 0; k < 128; ++k) s = fmaf(a1[k], w2[k * 64 + t], s);
        a2[t] = fmaxf(s, 0.f);
    }
    __syncthreads();
    if (t < 32) {
        float s = b3[t];
        for (int k = 0; k < 64; ++k) s = fmaf(a2[k], w3[k * 32 + t], s);
        a3[t] = fmaxf(s, 0.f);
    }
    __syncthreads();
    if (t < 16) {
        float s = b4[t];
        for (int k = 0; k < 32; ++k) s = fmaf(a3[k], w4[k * 16 + t], s);
        a4s[t] = fmaxf(s, 0.f);
    }
    __syncthreads();
    if (t == 0) {
        float s = b5[0];
        for (int k = 0; k < 16; ++k) s = fmaf(a4s[k], w5[k], s);
        out[g] = s;
    }
}

// ---------------------------------------------------------------------------
extern "C" void kernel_launch(void* const* d_in, const int* in_sizes, int n_in,
                              void* d_out, int out_size)
{
    const float* x     = (const float*)d_in[0];
    const int*   ei    = (const int*)d_in[1];
    const float* ea    = (const float*)d_in[2];
    const int*   batch = (const int*)d_in[3];
    const float* usr   = (const float*)d_in[4];
    const float* e1_w = (const float*)d_in[5],  *e1_b = (const float*)d_in[6];
    const float* n1_w1 = (const float*)d_in[7], *n1_b1 = (const float*)d_in[8];
    const float* n1_w2 = (const float*)d_in[9], *n1_b2 = (const float*)d_in[10];
    const float* e2_w = (const float*)d_in[11], *e2_b = (const float*)d_in[12];
    const float* n2_w1 = (const float*)d_in[13], *n2_b1 = (const float*)d_in[14];
    const float* n2_w2 = (const float*)d_in[15], *n2_b2 = (const float*)d_in[16];
    const float* h1_w = (const float*)d_in[17], *h1_b = (const float*)d_in[18];
    const float* h2_w = (const float*)d_in[19], *h2_b = (const float*)d_in[20];
    const float* h3_w = (const float*)d_in[21], *h3_b = (const float*)d_in[22];
    const float* h4_w = (const float*)d_in[23], *h4_b = (const float*)d_in[24];
    const float* h5_w = (const float*)d_in[25], *h5_b = (const float*)d_in[26];
    float* out = (float*)d_out;

    float *agg, *h, *poolbuf, *wt;
    cudaGetSymbolAddress((void**)&agg, g_agg);
    cudaGetSymbolAddress((void**)&h, g_h);
    cudaGetSymbolAddress((void**)&poolbuf, g_pool);
    cudaGetSymbolAddress((void**)&wt, g_wt);
    float* pool = poolbuf;
    float* cnt  = poolbuf + (size_t)Gg * 128;
    float* n1w1t = wt;
    float* n1w2t = wt + 4096;
    float* n2w1t = wt + 8192;
    float* n2w2t = wt + 16384;

    const int NODE1_SMEM = 26240 * 4;   // 104960 B -> 2 CTA/SM
    const int NODE2_SMEM = 51456 * 4;   // 205824 B -> 1 CTA/SM
    cudaFuncSetAttribute(node1_mma, cudaFuncAttributeMaxDynamicSharedMemorySize, NODE1_SMEM);
    cudaFuncSetAttribute(node2_mma, cudaFuncAttributeMaxDynamicSharedMemorySize, NODE2_SMEM);

    int aggN4 = Nn * 64 / 4;
    int poolN4 = Gg * 129 / 4;
    const int EDGE_GRID = 1184;

    transpose_w<<<128, 256>>>(n1_w1, n1_w2, n2_w1, n2_w2, wt);

    // layer 1
    zero_kernel<<<(aggN4 + 255) / 256, 256>>>((float4*)agg, aggN4);
    edge_kernel<<<EDGE_GRID, 256>>>(x, ei, ea, e1_w, e1_b, agg);
    node1_mma<<<296, 256, NODE1_SMEM>>>(x, agg, n1w1t, n1_b1, n1w2t, n1_b2, h);

    // layer 2
    zero_kernel<<<(aggN4 + 255) / 256, 256>>>((float4*)agg, aggN4);
    edge_kernel<<<EDGE_GRID, 256>>>(h, ei, ea, e2_w, e2_b, agg);
    zero_kernel<<<(poolN4 + 255) / 256, 256>>>((float4*)poolbuf, poolN4);
    node2_mma<<<148, 256, NODE2_SMEM>>>(h, agg, n2w1t, n2_b1, n2w2t, n2_b2, batch, pool, cnt);

    // head
    head_kernel<<<Gg, 128>>>(pool, cnt, usr,
                             h1_w, h1_b, h2_w, h2_b, h3_w, h3_b, h4_w, h4_b, h5_w, h5_b,
                             out);
}

// round 15
// speedup vs baseline: 1.4430x; 1.0095x over previous
#include <cuda_runtime.h>
#include <cstdint>

typedef unsigned int u32;

// Problem constants
static constexpr int Nn = 200000;
static constexpr int Ee = 400000;
static constexpr int Gg = 4096;
static constexpr int USR = 12;
static constexpr int NT = (Nn + 127) / 128;   // 1563 row tiles

// Scratch (device globals; no allocation allowed). Zero-initialized at load.
// agg is re-zeroed by its consumer (node1 for layer2, node2 for next replay),
// in a store-only loop AFTER the staging loads complete.
__device__ float g_agg[(size_t)Nn * 64];
__device__ float g_h[(size_t)Nn * 64];
__device__ float g_pool[(size_t)Gg * 129];
__device__ float g_wt[32768];   // tf32-converted transposed weights

// ---------------------------------------------------------------------------
__device__ __forceinline__ u32 tf32b(float x) {
    u32 u; asm("cvt.rna.tf32.f32 %0, %1;" : "=r"(u) : "f"(x)); return u;
}
__device__ __forceinline__ void mma_tf32(float& d0, float& d1, float& d2, float& d3,
                                         u32 a0, u32 a1, u32 a2, u32 a3, u32 b0, u32 b1) {
    asm volatile(
        "mma.sync.aligned.m16n8k8.row.col.f32.tf32.tf32.f32 "
        "{%0,%1,%2,%3},{%4,%5,%6,%7},{%8,%9},{%0,%1,%2,%3};"
        : "+f"(d0), "+f"(d1), "+f"(d2), "+f"(d3)
        : "r"(a0), "r"(a1), "r"(a2), "r"(a3), "r"(b0), "r"(b1));
}

// ---------------------------------------------------------------------------
__global__ void zero_kernel(float4* __restrict__ p, int n4) {
    int i = blockIdx.x * blockDim.x + threadIdx.x;
    if (i < n4) p[i] = make_float4(0.f, 0.f, 0.f, 0.f);
}

// transpose + tf32-convert node weights into g_wt
__global__ void transpose_w(const float* __restrict__ n1w1, const float* __restrict__ n1w2,
                            const float* __restrict__ n2w1, const float* __restrict__ n2w2,
                            float* __restrict__ wt)
{
    int i = blockIdx.x * blockDim.x + threadIdx.x;
    float v;
    if (i < 4096)       { int n = i >> 6, k = i & 63; v = n1w1[k * 64 + n]; }
    else if (i < 8192)  { int j = i - 4096;  int n = j >> 6, k = j & 63;  v = n1w2[k * 64 + n]; }
    else if (i < 16384) { int j = i - 8192;  int n = j >> 6, k = j & 63;  v = n2w1[k * 128 + n]; }
    else                { int j = i - 16384; int n = j >> 7, k = j & 127; v = n2w2[k * 128 + n]; }
    wt[i] = __uint_as_float(tf32b(v));
}

// ---------------------------------------------------------------------------
// Edge message + scatter:  agg[dst] += relu(x[src] + ea @ EW + eb)
// Warp-autonomous, software-pipelined.
__global__ __launch_bounds__(256) void edge_kernel(
    const float* __restrict__ xin, const int* __restrict__ ei,
    const float* __restrict__ ea, const float* __restrict__ ew,
    const float* __restrict__ eb, float* __restrict__ agg)
{
    __shared__ float sW[16 * 64];
    int tid = threadIdx.x;
    for (int i = tid; i < 1024; i += 256) sW[i] = ew[i];
    __syncthreads();

    int lane = tid & 31, half = lane >> 4, q = lane & 15;
    int warpG = blockIdx.x * 8 + (tid >> 5);
    int nW = gridDim.x * 8;
    float4 bias = ((const float4*)eb)[q];
    const unsigned mask = 0xFFFFFFFFu;
    int srcBase = half << 4;

    int p = warpG;
    if (p * 2 >= Ee) return;
    int e = p * 2 + half;                 // Ee even -> both halves valid
    int s = __ldg(&ei[e]);
    int d = __ldg(&ei[Ee + e]);
    float av = __ldg(&ea[(size_t)e * 16 + q]);
    float4 xv = *(const float4*)(xin + (size_t)s * 64 + q * 4);

    while (true) {
        int pn = p + nW;
        bool more = (pn * 2 < Ee);
        int sn = 0, dn = 0; float avn = 0.f; float4 xvn;
        if (more) {
            int en = pn * 2 + half;
            sn = __ldg(&ei[en]);
            dn = __ldg(&ei[Ee + en]);
            avn = __ldg(&ea[(size_t)en * 16 + q]);
            xvn = *(const float4*)(xin + (size_t)sn * 64 + q * 4);
        }

        float4 acc = bias;
#pragma unroll
        for (int k = 0; k < 16; ++k) {
            float a = __shfl_sync(mask, av, srcBase + k);
            float4 w = ((const float4*)(sW + k * 64))[q];
            acc.x = fmaf(a, w.x, acc.x);
            acc.y = fmaf(a, w.y, acc.y);
            acc.z = fmaf(a, w.z, acc.z);
            acc.w = fmaf(a, w.w, acc.w);
        }
        acc.x = fmaxf(acc.x + xv.x, 0.f);
        acc.y = fmaxf(acc.y + xv.y, 0.f);
        acc.z = fmaxf(acc.z + xv.z, 0.f);
        acc.w = fmaxf(acc.w + xv.w, 0.f);

        float* pp = agg + (size_t)d * 64 + q * 4;
        asm volatile("red.global.add.v4.f32 [%0], {%1,%2,%3,%4};"
                     :: "l"(pp), "f"(acc.x), "f"(acc.y), "f"(acc.z), "f"(acc.w)
                     : "memory");

        if (!more) break;
        s = sn; d = dn; av = avn; xv = xvn; p = pn;
    }
}

// ---------------------------------------------------------------------------
// node1 (tf32 mma.sync, persistent). Re-zeroes agg in a store-only loop
// AFTER the staging loads (drains during GEMM compute).
// smem u32: A1 @0 [128*68] | B1 @8704 [64*68] | A2 @13056 [128*68] |
//           B2 @21760 [64*68] | BI1 @26112 [64] | BI2 @26176 [64]
// OUT (float [128][64]) overlays A2 after GEMM2.
__global__ __launch_bounds__(256) void node1_mma(
    const float* __restrict__ xin, float* __restrict__ agg,
    const float* __restrict__ w1t, const float* __restrict__ b1,
    const float* __restrict__ w2t, const float* __restrict__ b2,
    float* __restrict__ hout)
{
    extern __shared__ u32 sm[];
    const int A1 = 0, B1 = 8704, A2 = 13056, B2 = 21760, BI1 = 26112, BI2 = 26176;

    int tid = threadIdx.x;
    // stage weights + biases ONCE
    for (int i = tid; i < 64 * 16; i += 256) {
        int r = i >> 4, c = (i & 15) * 4;
        float4 v = *(const float4*)(w1t + r * 64 + c);
        sm[B1 + r * 68 + c + 0] = __float_as_uint(v.x);
        sm[B1 + r * 68 + c + 1] = __float_as_uint(v.y);
        sm[B1 + r * 68 + c + 2] = __float_as_uint(v.z);
        sm[B1 + r * 68 + c + 3] = __float_as_uint(v.w);
        float4 w = *(const float4*)(w2t + r * 64 + c);
        sm[B2 + r * 68 + c + 0] = __float_as_uint(w.x);
        sm[B2 + r * 68 + c + 1] = __float_as_uint(w.y);
        sm[B2 + r * 68 + c + 2] = __float_as_uint(w.z);
        sm[B2 + r * 68 + c + 3] = __float_as_uint(w.w);
    }
    if (tid < 64) ((float*)(sm + BI1))[tid] = b1[tid];
    else if (tid < 128) ((float*)(sm + BI2))[tid - 64] = b2[tid - 64];

    int wid = tid >> 5, lane = tid & 31, g = lane >> 2, t = lane & 3;
    int wr = wid * 16;
    const float4 z4 = make_float4(0.f, 0.f, 0.f, 0.f);

    for (int tile = blockIdx.x; tile < NT; tile += gridDim.x) {
        int row0 = tile * 128;
        // stage A1 = tf32(x+agg)  (pure load batch; no stores interleaved)
        for (int i = tid; i < 128 * 16; i += 256) {
            int r = i >> 4, c = (i & 15) * 4;
            int gr = row0 + r; if (gr >= Nn) gr = Nn - 1;
            float4 xv = *(const float4*)(xin + (size_t)gr * 64 + c);
            float4 av = *(const float4*)(agg + (size_t)gr * 64 + c);
            sm[A1 + r * 68 + c + 0] = tf32b(xv.x + av.x);
            sm[A1 + r * 68 + c + 1] = tf32b(xv.y + av.y);
            sm[A1 + r * 68 + c + 2] = tf32b(xv.z + av.z);
            sm[A1 + r * 68 + c + 3] = tf32b(xv.w + av.w);
        }
        __syncthreads();
        // re-zero own tile's agg rows (store-only; drains under GEMM)
        for (int i = tid; i < 128 * 16; i += 256) {
            int r = i >> 4, c = (i & 15) * 4;
            int gr0 = row0 + r;
            if (gr0 < Nn) *(float4*)(agg + (size_t)gr0 * 64 + c) = z4;
        }

        float d[8][4];
#pragma unroll
        for (int n = 0; n < 8; ++n) { d[n][0] = d[n][1] = d[n][2] = d[n][3] = 0.f; }

        // GEMM1
#pragma unroll
        for (int ks = 0; ks < 8; ++ks) {
            int k0 = ks * 8;
            u32 a0 = sm[A1 + (wr + g) * 68 + k0 + t];
            u32 a1 = sm[A1 + (wr + g + 8) * 68 + k0 + t];
            u32 a2 = sm[A1 + (wr + g) * 68 + k0 + t + 4];
            u32 a3 = sm[A1 + (wr + g + 8) * 68 + k0 + t + 4];
#pragma unroll
            for (int nt = 0; nt < 8; ++nt) {
                u32 b0 = sm[B1 + (nt * 8 + g) * 68 + k0 + t];
                u32 bv = sm[B1 + (nt * 8 + g) * 68 + k0 + t + 4];
                mma_tf32(d[nt][0], d[nt][1], d[nt][2], d[nt][3], a0, a1, a2, a3, b0, bv);
            }
        }
        // epi1 -> A2 (own rows only)
        {
            const float* bb = (const float*)(sm + BI1);
#pragma unroll
            for (int nt = 0; nt < 8; ++nt) {
                int c = nt * 8 + t * 2;
                sm[A2 + (wr + g) * 68 + c]     = tf32b(fmaxf(d[nt][0] + bb[c], 0.f));
                sm[A2 + (wr + g) * 68 + c + 1] = tf32b(fmaxf(d[nt][1] + bb[c + 1], 0.f));
                sm[A2 + (wr + g + 8) * 68 + c]     = tf32b(fmaxf(d[nt][2] + bb[c], 0.f));
                sm[A2 + (wr + g + 8) * 68 + c + 1] = tf32b(fmaxf(d[nt][3] + bb[c + 1], 0.f));
                d[nt][0] = d[nt][1] = d[nt][2] = d[nt][3] = 0.f;
            }
        }
        // GEMM2 (A rows own-warp; B2 static) — no sync needed
#pragma unroll
        for (int ks = 0; ks < 8; ++ks) {
            int k0 = ks * 8;
            u32 a0 = sm[A2 + (wr + g) * 68 + k0 + t];
            u32 a1 = sm[A2 + (wr + g + 8) * 68 + k0 + t];
            u32 a2 = sm[A2 + (wr + g) * 68 + k0 + t + 4];
            u32 a3 = sm[A2 + (wr + g + 8) * 68 + k0 + t + 4];
#pragma unroll
            for (int nt = 0; nt < 8; ++nt) {
                u32 b0 = sm[B2 + (nt * 8 + g) * 68 + k0 + t];
                u32 bv = sm[B2 + (nt * 8 + g) * 68 + k0 + t + 4];
                mma_tf32(d[nt][0], d[nt][1], d[nt][2], d[nt][3], a0, a1, a2, a3, b0, bv);
            }
        }
        __syncthreads();   // all warps done reading A2 before OUT overlays it
        // epi2: relu(+b2) -> OUT floats (overlay A2)
        {
            float* outF = (float*)(sm + A2);
            const float* bb = (const float*)(sm + BI2);
#pragma unroll
            for (int nt = 0; nt < 8; ++nt) {
                int c = nt * 8 + t * 2;
                outF[(wr + g) * 64 + c]     = fmaxf(d[nt][0] + bb[c], 0.f);
                outF[(wr + g) * 64 + c + 1] = fmaxf(d[nt][1] + bb[c + 1], 0.f);
                outF[(wr + g + 8) * 64 + c]     = fmaxf(d[nt][2] + bb[c], 0.f);
                outF[(wr + g + 8) * 64 + c + 1] = fmaxf(d[nt][3] + bb[c + 1], 0.f);
            }
        }
        __syncthreads();
        // coalesced store
        {
            const float* outF = (const float*)(sm + A2);
            for (int i = tid; i < 128 * 16; i += 256) {
                int r = i >> 4, c = (i & 15) * 4;
                int gr = row0 + r;
                if (gr < Nn) *(float4*)(hout + (size_t)gr * 64 + c) = *(const float4*)(outF + r * 64 + c);
            }
        }
        __syncthreads();   // store done before next iter's epi1 overwrites A2
    }
}

// ---------------------------------------------------------------------------
// node2 (tf32 mma.sync, persistent) + pooling; re-zeroes agg for next replay.
// smem u32: A1 @0 [128*68] | B1 @8704 [128*68] | A2 @17408 [128*132] |
//           B2 @34304 [128*132] | BI1 @51200 [128] | BI2 @51328 [128]
// OUT (float [128][128]=16384) overlays A2 (16896).
__global__ __launch_bounds__(256) void node2_mma(
    const float* __restrict__ hin, float* __restrict__ agg,
    const float* __restrict__ w1t, const float* __restrict__ b1,
    const float* __restrict__ w2t, const float* __restrict__ b2,
    const int* __restrict__ batch,
    float* __restrict__ pool, float* __restrict__ cnt)
{
    extern __shared__ u32 sm[];
    const int A1 = 0, B1 = 8704, A2 = 17408, B2 = 34304, BI1 = 51200, BI2 = 51328;

    int tid = threadIdx.x;
    for (int i = tid; i < 128 * 16; i += 256) {   // B1 = w1t [128][64]
        int r = i >> 4, c = (i & 15) * 4;
        float4 v = *(const float4*)(w1t + r * 64 + c);
        sm[B1 + r * 68 + c + 0] = __float_as_uint(v.x);
        sm[B1 + r * 68 + c + 1] = __float_as_uint(v.y);
        sm[B1 + r * 68 + c + 2] = __float_as_uint(v.z);
        sm[B1 + r * 68 + c + 3] = __float_as_uint(v.w);
    }
    for (int i = tid; i < 128 * 32; i += 256) {   // B2 = w2t [128][128]
        int r = i >> 5, c = (i & 31) * 4;
        float4 v = *(const float4*)(w2t + r * 128 + c);
        sm[B2 + r * 132 + c + 0] = __float_as_uint(v.x);
        sm[B2 + r * 132 + c + 1] = __float_as_uint(v.y);
        sm[B2 + r * 132 + c + 2] = __float_as_uint(v.z);
        sm[B2 + r * 132 + c + 3] = __float_as_uint(v.w);
    }
    if (tid < 128) ((float*)(sm + BI1))[tid] = b1[tid];
    else ((float*)(sm + BI2))[tid - 128] = b2[tid - 128];

    int wid = tid >> 5, lane = tid & 31, g = lane >> 2, t = lane & 3;
    int wr = wid * 16;
    const float4 z4 = make_float4(0.f, 0.f, 0.f, 0.f);

    for (int tile = blockIdx.x; tile < NT; tile += gridDim.x) {
        int row0 = tile * 128;
        // staging (pure load batch)
        for (int i = tid; i < 128 * 16; i += 256) {
            int r = i >> 4, c = (i & 15) * 4;
            int gr = row0 + r; if (gr >= Nn) gr = Nn - 1;
            float4 xv = *(const float4*)(hin + (size_t)gr * 64 + c);
            float4 av = *(const float4*)(agg + (size_t)gr * 64 + c);
            sm[A1 + r * 68 + c + 0] = tf32b(xv.x + av.x);
            sm[A1 + r * 68 + c + 1] = tf32b(xv.y + av.y);
            sm[A1 + r * 68 + c + 2] = tf32b(xv.z + av.z);
            sm[A1 + r * 68 + c + 3] = tf32b(xv.w + av.w);
        }
        __syncthreads();
        // re-zero own tile's agg rows (store-only; drains under GEMM)
        for (int i = tid; i < 128 * 16; i += 256) {
            int r = i >> 4, c = (i & 15) * 4;
            int gr0 = row0 + r;
            if (gr0 < Nn) *(float4*)(agg + (size_t)gr0 * 64 + c) = z4;
        }

        float d[16][4];
#pragma unroll
        for (int n = 0; n < 16; ++n) { d[n][0] = d[n][1] = d[n][2] = d[n][3] = 0.f; }

        // GEMM1: [128x64] @ [64x128]
#pragma unroll
        for (int ks = 0; ks < 8; ++ks) {
            int k0 = ks * 8;
            u32 a0 = sm[A1 + (wr + g) * 68 + k0 + t];
            u32 a1 = sm[A1 + (wr + g + 8) * 68 + k0 + t];
            u32 a2 = sm[A1 + (wr + g) * 68 + k0 + t + 4];
            u32 a3 = sm[A1 + (wr + g + 8) * 68 + k0 + t + 4];
#pragma unroll
            for (int nt = 0; nt < 16; ++nt) {
                u32 b0 = sm[B1 + (nt * 8 + g) * 68 + k0 + t];
                u32 bv = sm[B1 + (nt * 8 + g) * 68 + k0 + t + 4];
                mma_tf32(d[nt][0], d[nt][1], d[nt][2], d[nt][3], a0, a1, a2, a3, b0, bv);
            }
        }
        // epi1 -> A2 (own rows)
        {
            const float* bb = (const float*)(sm + BI1);
#pragma unroll
            for (int nt = 0; nt < 16; ++nt) {
                int c = nt * 8 + t * 2;
                sm[A2 + (wr + g) * 132 + c]     = tf32b(fmaxf(d[nt][0] + bb[c], 0.f));
                sm[A2 + (wr + g) * 132 + c + 1] = tf32b(fmaxf(d[nt][1] + bb[c + 1], 0.f));
                sm[A2 + (wr + g + 8) * 132 + c]     = tf32b(fmaxf(d[nt][2] + bb[c], 0.f));
                sm[A2 + (wr + g + 8) * 132 + c + 1] = tf32b(fmaxf(d[nt][3] + bb[c + 1], 0.f));
                d[nt][0] = d[nt][1] = d[nt][2] = d[nt][3] = 0.f;
            }
        }
        // GEMM2: [128x128] @ [128x128]  (A rows own-warp; B2 static)
#pragma unroll 4
        for (int ks = 0; ks < 16; ++ks) {
            int k0 = ks * 8;
            u32 a0 = sm[A2 + (wr + g) * 132 + k0 + t];
            u32 a1 = sm[A2 + (wr + g + 8) * 132 + k0 + t];
            u32 a2 = sm[A2 + (wr + g) * 132 + k0 + t + 4];
            u32 a3 = sm[A2 + (wr + g + 8) * 132 + k0 + t + 4];
#pragma unroll
            for (int nt = 0; nt < 16; ++nt) {
                u32 b0 = sm[B2 + (nt * 8 + g) * 132 + k0 + t];
                u32 bv = sm[B2 + (nt * 8 + g) * 132 + k0 + t + 4];
                mma_tf32(d[nt][0], d[nt][1], d[nt][2], d[nt][3], a0, a1, a2, a3, b0, bv);
            }
        }
        __syncthreads();   // all warps done reading A2 before OUT overlays it
        // epi2: +b2 -> OUT floats (overlay A2)
        {
            float* outF = (float*)(sm + A2);
            const float* bb = (const float*)(sm + BI2);
#pragma unroll
            for (int nt = 0; nt < 16; ++nt) {
                int c = nt * 8 + t * 2;
                outF[(wr + g) * 128 + c]     = d[nt][0] + bb[c];
                outF[(wr + g) * 128 + c + 1] = d[nt][1] + bb[c + 1];
                outF[(wr + g + 8) * 128 + c]     = d[nt][2] + bb[c];
                outF[(wr + g + 8) * 128 + c + 1] = d[nt][3] + bb[c + 1];
            }
        }
        __syncthreads();
        // pooled scatter
        {
            const float* outF = (const float*)(sm + A2);
            int tx = tid & 31, ty = tid >> 5;
            int c0 = tx * 4;
#pragma unroll
            for (int i = 0; i < 16; ++i) {
                int r = ty * 16 + i;
                int gr = row0 + r;
                if (gr < Nn) {
                    int gg = batch[gr];
                    float4 v = *(const float4*)(outF + r * 128 + c0);
                    float* p = pool + (size_t)gg * 128 + c0;
                    asm volatile("red.global.add.v4.f32 [%0], {%1,%2,%3,%4};"
                                 :: "l"(p), "f"(v.x), "f"(v.y), "f"(v.z), "f"(v.w) : "memory");
                }
            }
            if (tid < 128) {
                int gr = row0 + tid;
                if (gr < Nn) atomicAdd(&cnt[batch[gr]], 1.0f);
            }
        }
        __syncthreads();   // scatter done before next iter's epi1 overwrites A2
    }
}

// ---------------------------------------------------------------------------
// Head MLP: z = [pool/cnt, usr]; 140 ->128 ->64 ->32 ->16 ->1
__global__ __launch_bounds__(128) void head_kernel(
    const float* __restrict__ pool, const float* __restrict__ cnt,
    const float* __restrict__ usr,
    const float* __restrict__ w1, const float* __restrict__ b1,
    const float* __restrict__ w2, const float* __restrict__ b2,
    const float* __restrict__ w3, const float* __restrict__ b3,
    const float* __restrict__ w4, const float* __restrict__ b4,
    const float* __restrict__ w5, const float* __restrict__ b5,
    float* __restrict__ out)
{
    __shared__ float z[140];
    __shared__ float a1[128];
    __shared__ float a2[64];
    __shared__ float a3[32];
    __shared__ float a4s[16];

    int g = blockIdx.x, t = threadIdx.x;
    float inv = 1.0f / fmaxf(cnt[g], 1.0f);
    z[t] = pool[(size_t)g * 128 + t] * inv;
    if (t < USR) z[128 + t] = usr[(size_t)g * USR + t];
    __syncthreads();

    {
        float s = b1[t];
        for (int k = 0; k < 140; ++k) s = fmaf(z[k], w1[k * 128 + t], s);
        a1[t] = fmaxf(s, 0.f);
    }
    __syncthreads();
    if (t < 64) {
        float s = b2[t];
        for (int k = 0; k < 128; ++k) s = fmaf(a1[k], w2[k * 64 + t], s);
        a2[t] = fmaxf(s, 0.f);
    }
    __syncthreads();
    if (t < 32) {
        float s = b3[t];
        for (int k = 0; k < 64; ++k) s = fmaf(a2[k], w3[k * 32 + t], s);
        a3[t] = fmaxf(s, 0.f);
    }
    __syncthreads();
    if (t < 16) {
        float s = b4[t];
        for (int k = 0; k < 32; ++k) s = fmaf(a3[k], w4[k * 16 + t], s);
        a4s[t] = fmaxf(s, 0.f);
    }
    __syncthreads();
    if (t == 0) {
        float s = b5[0];
        for (int k = 0; k < 16; ++k) s = fmaf(a4s[k], w5[k], s);
        out[g] = s;
    }
}

// ---------------------------------------------------------------------------
extern "C" void kernel_launch(void* const* d_in, const int* in_sizes, int n_in,
                              void* d_out, int out_size)
{
    const float* x     = (const float*)d_in[0];
    const int*   ei    = (const int*)d_in[1];
    const float* ea    = (const float*)d_in[2];
    const int*   batch = (const int*)d_in[3];
    const float* usr   = (const float*)d_in[4];
    const float* e1_w = (const float*)d_in[5],  *e1_b = (const float*)d_in[6];
    const float* n1_w1 = (const float*)d_in[7], *n1_b1 = (const float*)d_in[8];
    const float* n1_w2 = (const float*)d_in[9], *n1_b2 = (const float*)d_in[10];
    const float* e2_w = (const float*)d_in[11], *e2_b = (const float*)d_in[12];
    const float* n2_w1 = (const float*)d_in[13], *n2_b1 = (const float*)d_in[14];
    const float* n2_w2 = (const float*)d_in[15], *n2_b2 = (const float*)d_in[16];
    const float* h1_w = (const float*)d_in[17], *h1_b = (const float*)d_in[18];
    const float* h2_w = (const float*)d_in[19], *h2_b = (const float*)d_in[20];
    const float* h3_w = (const float*)d_in[21], *h3_b = (const float*)d_in[22];
    const float* h4_w = (const float*)d_in[23], *h4_b = (const float*)d_in[24];
    const float* h5_w = (const float*)d_in[25], *h5_b = (const float*)d_in[26];
    float* out = (float*)d_out;

    float *agg, *h, *poolbuf, *wt;
    cudaGetSymbolAddress((void**)&agg, g_agg);
    cudaGetSymbolAddress((void**)&h, g_h);
    cudaGetSymbolAddress((void**)&poolbuf, g_pool);
    cudaGetSymbolAddress((void**)&wt, g_wt);
    float* pool = poolbuf;
    float* cnt  = poolbuf + (size_t)Gg * 128;
    float* n1w1t = wt;
    float* n1w2t = wt + 4096;
    float* n2w1t = wt + 8192;
    float* n2w2t = wt + 16384;

    const int NODE1_SMEM = 26240 * 4;   // 104960 B -> 2 CTA/SM
    const int NODE2_SMEM = 51456 * 4;   // 205824 B -> 1 CTA/SM
    cudaFuncSetAttribute(node1_mma, cudaFuncAttributeMaxDynamicSharedMemorySize, NODE1_SMEM);
    cudaFuncSetAttribute(node2_mma, cudaFuncAttributeMaxDynamicSharedMemorySize, NODE2_SMEM);

    int poolN4 = Gg * 129 / 4;
    const int EDGE_GRID = 1184;

    transpose_w<<<128, 256>>>(n1_w1, n1_w2, n2_w1, n2_w2, wt);
    zero_kernel<<<(poolN4 + 255) / 256, 256>>>((float4*)poolbuf, poolN4);

    // layer 1 (agg zero: load-time init on first call; re-zeroed by node2 each replay)
    edge_kernel<<<EDGE_GRID, 256>>>(x, ei, ea, e1_w, e1_b, agg);
    node1_mma<<<296, 256, NODE1_SMEM>>>(x, agg, n1w1t, n1_b1, n1w2t, n1_b2, h);
    // node1 re-zeroed agg for layer 2

    // layer 2
    edge_kernel<<<EDGE_GRID, 256>>>(h, ei, ea, e2_w, e2_b, agg);
    node2_mma<<<148, 256, NODE2_SMEM>>>(h, agg, n2w1t, n2_b1, n2w2t, n2_b2, batch, pool, cnt);
    // node2 re-zeroed agg for next replay

    // head
    head_kernel<<<Gg, 128>>>(pool, cnt, usr,
                             h1_w, h1_b, h2_w, h2_b, h3_w, h3_b, h4_w, h4_b, h5_w, h5_b,
                             out);
}